// round 3
// baseline (speedup 1.0000x reference)
#include <cuda_runtime.h>
#include <cstdint>

#define BB    2048
#define SS    201
#define HALF  100
#define DD    128
#define ROWS  (BB*SS)          /* 411648 */
#define A_EL  (ROWS*DD)        /* 52697088 : elems of x_embedding (== pos_enc) */

// scratch: visited_time as int32 for the gather kernel (static device array: allowed)
__device__ int g_visited[ROWS];

// ---------------------------------------------------------------------------
// Kernel 1: per-batch pointer chase over the solution cycle + incremental
// stack + exact top_k(...,2) via sortable integer keys.
// One warp per batch. key = t*512 + (511 - slot):
//   t = -1  (popped / -0.01)  -> key = -1 - slot   (smaller slot => larger key)
//   t = 0   (slot 0, value 0) -> key = 511
//   t = i+1 (push time)       -> key > 511, strictly increasing, distinct
// max / 2nd-max of keys == lax.top_k(stacks, 2) indices (stable tie-break).
// ---------------------------------------------------------------------------
__global__ void __launch_bounds__(128)
chase_kernel(const int* __restrict__ sol32,
             float*  __restrict__ out_vt,
             float2* __restrict__ out_t2,
             int write_vt, int write_t2)
{
    __shared__ int s_sol[4][SS + 7];
    const int warp = threadIdx.x >> 5;
    const int lane = threadIdx.x & 31;
    const int b    = blockIdx.x * 4 + warp;

    // dtype sniff: int64 viewed as int32 has zero odd words; an int32 row has
    // exactly one zero in it, so words 1,3,5 cannot all be zero.
    const bool is_i64 = (sol32[1] == 0) & (sol32[3] == 0) & (sol32[5] == 0);

    if (is_i64) {
        const int* p = sol32 + 2 * b * SS;
        for (int i = lane; i < SS; i += 32) s_sol[warp][i] = p[2 * i];
    } else {
        const int* p = sol32 + b * SS;
        for (int i = lane; i < SS; i += 32) s_sol[warp][i] = p[i];
    }
    __syncwarp();

    const int NEG = (-2147483647 - 1);
    // lane owns slots lane, lane+32, lane+64, lane+96 (valid while <= 100)
    int key0 = (lane == 0) ? 511 : (-1 - lane);
    int key1 = -1 - (lane + 32);
    int key2 = -1 - (lane + 64);
    int key3 = (lane + 96 <= HALF) ? (-1 - (lane + 96)) : NEG;

    int pre  = 0;
    const int base = b * SS;

    for (int i = 0; i < SS; i++) {
        const int cur = s_sol[warp][pre];
        pre = cur;
        const int vt = i + 1;

        if (cur != 0) {
            const int pos = (cur > HALF) ? (cur - HALF) : cur;
            const int nk  = (cur > HALF) ? (-1 - pos) : (vt * 512 + 511 - pos);
            if ((pos & 31) == lane) {
                const int k = pos >> 5;
                if      (k == 0) key0 = nk;
                else if (k == 1) key1 = nk;
                else if (k == 2) key2 = nk;
                else             key3 = nk;
            }
        }

        // local top2 of 4 keys
        int a  = max(key0, key1), bl = min(key0, key1);
        int c  = max(key2, key3), dl = min(key2, key3);
        int m1 = max(a, c);
        int m2 = max(min(a, c), max(bl, dl));

        // warp butterfly top2-merge
        #pragma unroll
        for (int off = 16; off; off >>= 1) {
            int o1 = __shfl_xor_sync(0xffffffffu, m1, off);
            int o2 = __shfl_xor_sync(0xffffffffu, m2, off);
            int n1 = max(m1, o1);
            m2 = max(min(m1, o1), max(m2, o2));
            m1 = n1;
        }

        if (lane == 0) {
            const int row = base + cur;
            g_visited[row] = vt;
            if (write_vt) out_vt[row] = (float)vt;
            if (write_t2) out_t2[row] = make_float2((float)(511 - (m1 & 511)),
                                                    (float)(511 - (m2 & 511)));
        }
    }
}

// ---------------------------------------------------------------------------
// Kernel 2: x_embedding = x @ W^T  and  pos_enc = pattern[visited % S].
// One warp per (b,s) row; one float4 of each output per thread. Pure BW.
// Streaming stores (.cs) keep the 421 MB write stream from evicting the
// cache-resident pattern/W tables.
// ---------------------------------------------------------------------------
__global__ void __launch_bounds__(256)
embed_kernel(const float2* __restrict__ x2,
             const float4* __restrict__ W4,
             const float4* __restrict__ patt4,
             float4* __restrict__ out_emb,
             float4* __restrict__ out_pos,
             int write_pos)
{
    const int gid = blockIdx.x * 256 + threadIdx.x;   // < ROWS*32
    const int r   = gid >> 5;                          // row (b*S + s)
    const int q   = gid & 31;                          // float4 index in dim

    const float2 xv  = __ldcs(&x2[r]);                 // read-once
    const float4 w01 = __ldg(&W4[2 * q]);              // W[c..c+1][0..1]
    const float4 w23 = __ldg(&W4[2 * q + 1]);          // W[c+2..c+3][0..1]

    float4 e;
    e.x = xv.x * w01.x + xv.y * w01.y;
    e.y = xv.x * w01.z + xv.y * w01.w;
    e.z = xv.x * w23.x + xv.y * w23.y;
    e.w = xv.x * w23.z + xv.y * w23.w;
    __stcs(&out_emb[r * 32 + q], e);

    if (write_pos) {
        const int vt = g_visited[r];                   // 1..201
        const int p  = (vt >= SS) ? (vt - SS) : vt;    // == vt % 201
        __stcs(&out_pos[r * 32 + q], __ldg(&patt4[p * 32 + q]));
    }
}

// ---------------------------------------------------------------------------
extern "C" void kernel_launch(void* const* d_in, const int* in_sizes, int n_in,
                              void* d_out, int out_size)
{
    const float* x   = nullptr;
    const int*   sol = nullptr;
    const float* W   = nullptr;
    const float* pat = nullptr;

    for (int i = 0; i < n_in; i++) {
        switch (in_sizes[i]) {
            case ROWS * 2: x   = (const float*)d_in[i]; break;  // 823296  : x
            case ROWS:     sol = (const int*)  d_in[i]; break;  // 411648  : solutions
            case 256:      W   = (const float*)d_in[i]; break;  //          W
            case SS * DD:  pat = (const float*)d_in[i]; break;  // 25728   : pattern
            default: break;
        }
    }

    float* out = (float*)d_out;

    const int write_pos = (out_size >= 2 * A_EL) ? 1 : 0;
    const int write_vt  = (out_size >= 2 * A_EL + ROWS) ? 1 : 0;
    const int write_t2  = (out_size >= 2 * A_EL + 3 * ROWS) ? 1 : 0;

    float*  out_vt = out + (size_t)2 * A_EL;
    float2* out_t2 = (float2*)(out + (size_t)2 * A_EL + ROWS);

    chase_kernel<<<BB / 4, 128>>>(sol, out_vt, out_t2, write_vt, write_t2);

    embed_kernel<<<(ROWS * 32) / 256, 256>>>(
        (const float2*)x, (const float4*)W, (const float4*)pat,
        (float4*)out, (float4*)(out + (size_t)A_EL), write_pos);
}